// round 9
// baseline (speedup 1.0000x reference)
#include <cuda_runtime.h>
#include <cuda_bf16.h>
#include <cstdint>

#define NTOK 8192
#define EDIM 64
#define SCALE 0.35355339059327373f   // 1/sqrt(8)
#define NPART 4

// packed bf16x2 words: [row][32 words], SW128-swizzled 16B chunks within 128B rows.
__device__ uint32_t g_qh[NTOK*32];
__device__ uint32_t g_kh[NTOK*32];
__device__ uint32_t g_vh[NTOK*32];
__device__ float    g_opart[NPART][NTOK][EDIM];   // unnormalized O per KV-part
__device__ float    g_lpart[NPART][NTOK];         // softmax denominator per KV-part

// ======================= helpers =======================
__device__ __forceinline__ uint32_t smem_u32(const void* p) {
    uint32_t a;
    asm("{ .reg .u64 t; cvta.to.shared.u64 t, %1; cvt.u32.u64 %0, t; }" : "=r"(a) : "l"(p));
    return a;
}
__device__ __forceinline__ void cp16(uint32_t dst, const void* src) {
    asm volatile("{ .reg .u64 g; cvta.to.global.u64 g, %1; cp.async.cg.shared.global [%0], [g], 16; }"
                 :: "r"(dst), "l"(src) : "memory");
}
#define CP_COMMIT() asm volatile("cp.async.commit_group;" ::: "memory")
#define CP_WAIT(n)  asm volatile("cp.async.wait_group %0;" :: "n"(n) : "memory")

#define LDSM4(r, a) \
    asm volatile("ldmatrix.sync.aligned.m8n8.x4.shared.b16 {%0,%1,%2,%3}, [%4];" \
        : "=r"((r)[0]), "=r"((r)[1]), "=r"((r)[2]), "=r"((r)[3]) : "r"(a))
#define LDSM4T(r, a) \
    asm volatile("ldmatrix.sync.aligned.m8n8.x4.trans.shared.b16 {%0,%1,%2,%3}, [%4];" \
        : "=r"((r)[0]), "=r"((r)[1]), "=r"((r)[2]), "=r"((r)[3]) : "r"(a))

#define MMA(c, a, b0, b1) \
    asm volatile("mma.sync.aligned.m16n8k16.row.col.f32.bf16.bf16.f32 " \
        "{%0,%1,%2,%3}, {%4,%5,%6,%7}, {%8,%9}, {%0,%1,%2,%3};" \
        : "+f"((c)[0]), "+f"((c)[1]), "+f"((c)[2]), "+f"((c)[3]) \
        : "r"((a)[0]), "r"((a)[1]), "r"((a)[2]), "r"((a)[3]), "r"(b0), "r"(b1))

// swizzled smem address: 128B rows, 16B chunk index XOR (row&7)
__device__ __forceinline__ uint32_t swadr(uint32_t base, int row, int bytecol) {
    return base + row*128 + ((((bytecol >> 4) ^ (row & 7)) << 4));
}
__device__ __forceinline__ uint32_t pack2(float a, float b) {
    __nv_bfloat162 p = __floats2bfloat162_rn(a, b);    // x=a (low), y=b (high)
    return *reinterpret_cast<uint32_t*>(&p);
}

// smem: Qh 0..16K (128 rows) ; buf b (b=0..2) at 16384 + b*16384 : [Kh 8K | Vh 8K]
#define SBUF(b)    (16384 + (b)*16384)
#define SMEM_FLASH 65536

// ---------------- Kernel 1: QKV projection + quantum map + bf16 packing ----------------
// 256 thr, 32 rows/block; thread: row rg x cols c0..c0+7.
__global__ void __launch_bounds__(256) qkv_kernel(
    const float* __restrict__ x,
    const float* __restrict__ wq, const float* __restrict__ bq,
    const float* __restrict__ wk, const float* __restrict__ bk,
    const float* __restrict__ wv, const float* __restrict__ bv,
    const float* __restrict__ theta)
{
    __shared__ float wtT[64*64];   // [d][col] (transposed: per-warp broadcast float4)
    __shared__ float xs[32*68];    // [row][d] stride 68 (16B-aligned, conflict-free)
    __shared__ float bs[64];
    __shared__ float cs[64];

    const int tid  = threadIdx.x;
    const int m    = blockIdx.y;
    const int row0 = blockIdx.x * 32;

    const float* w  = (m == 0) ? wq : ((m == 1) ? wk : wv);
    const float* bb = (m == 0) ? bq : ((m == 1) ? bk : bv);
    for (int i = tid; i < 4096; i += 256) {
        int col = i >> 6, d = i & 63;
        wtT[d*64 + col] = w[i];
    }
    if (tid < 64) {
        bs[tid] = bb[tid];
        cs[tid] = ((m == 0) ? SCALE : 1.0f) * __cosf(theta[tid]);
    }
    for (int i = tid; i < 2048; i += 256)
        xs[(i >> 6)*68 + (i & 63)] = x[(size_t)row0*64 + i];
    __syncthreads();

    const int rg = tid & 31;
    const int c0 = (tid >> 5) * 8;

    float acc[8];
    #pragma unroll
    for (int j = 0; j < 8; j++) acc[j] = bs[c0 + j];

    #pragma unroll
    for (int d4 = 0; d4 < 64; d4 += 4) {
        float4 xa = *reinterpret_cast<float4*>(&xs[rg*68 + d4]);
        float xr[4] = {xa.x, xa.y, xa.z, xa.w};
        #pragma unroll
        for (int j = 0; j < 4; j++) {
            float4 wA = *reinterpret_cast<float4*>(&wtT[(d4 + j)*64 + c0]);
            float4 wB = *reinterpret_cast<float4*>(&wtT[(d4 + j)*64 + c0 + 4]);
            float wv8[8] = {wA.x, wA.y, wA.z, wA.w, wB.x, wB.y, wB.z, wB.w};
            #pragma unroll
            for (int k = 0; k < 8; k++)
                acc[k] = fmaf(xr[j], wv8[k], acc[k]);
        }
    }

    uint32_t* dst = (m == 0) ? g_qh : ((m == 1) ? g_kh : g_vh);
    const int gr = row0 + rg;
    float v[8];
    #pragma unroll
    for (int j = 0; j < 8; j++)
        v[j] = cs[c0 + j] * __cosf(acc[j]);
    const int wd0 = ((((c0 >> 3) ^ (gr & 7)) << 2));
    #pragma unroll
    for (int p = 0; p < 4; p++)
        dst[gr*32 + wd0 + p] = pack2(v[2*p], v[2*p + 1]);
}

// ---------------- tile copy: 64 keys x (Kh, Vh), pre-swizzled ----------------
__device__ __forceinline__ void copy_tile(uint32_t sb, int tid, int buf, int kt) {
    #pragma unroll
    for (int j = 0; j < 4; j++) {
        int c = j*256 + tid;        // 0..1023
        int arr = c >> 9;           // 0:kh 1:vh (constant per j)
        int rem = c & 511;
        int row = rem >> 3, ch = rem & 7;
        const uint32_t* sp = arr ? g_vh : g_kh;
        cp16(sb + SBUF(buf) + arr*8192 + row*128 + ch*16,
             sp + (size_t)(kt*64 + row)*32 + ch*4);
    }
}

// ---------------- Kernel 2: bf16 flash, 128-row Q tiles, split-KV x4 ----------------
__global__ void __launch_bounds__(256, 2) flash_kernel()
{
    extern __shared__ char smem[];
    uint32_t sb = smem_u32(smem);
    const int tid  = threadIdx.x;
    const int wid  = tid >> 5;
    const int lane = tid & 31;
    const int qb   = blockIdx.x >> 2;       // 128 q-rows per CTA
    const int part = blockIdx.x & 3;        // KV quarter
    const int kt0  = part * 32;             // 32 64-key tiles per part

    // ---- prologue copies: Qh (16KB), tiles 0,1 ----
    #pragma unroll
    for (int j = 0; j < 4; j++) {
        int c = j*256 + tid;
        int row = c >> 3, ch = c & 7;
        cp16(sb + row*128 + ch*16, g_qh + (size_t)(qb*128 + row)*32 + ch*4);
    }
    CP_COMMIT();
    copy_tile(sb, tid, 0, kt0 + 0); CP_COMMIT();
    copy_tile(sb, tid, 1, kt0 + 1); CP_COMMIT();
    CP_WAIT(2);                  // Q landed
    __syncthreads();

    // ---- Q A-fragments (persistent): warp owns rows wid*16..+15 ----
    uint32_t qh[4][4];
    {
        const int row = wid*16 + (lane & 15);
        const int cb  = (lane >> 4) * 16;
        #pragma unroll
        for (int kc = 0; kc < 4; kc++)
            LDSM4(qh[kc], swadr(sb, row, 32*kc + cb));
    }

    float o[8][4];
    #pragma unroll
    for (int db = 0; db < 8; db++)
        #pragma unroll
        for (int i = 0; i < 4; i++) o[db][i] = 0.f;
    float lg = 0.f, lg8 = 0.f;

    const int li = lane & 7, ls = lane >> 3;
    const int lr = (lane >> 3) & 1, lc = lane >> 4;

    int b = 0;
    #pragma unroll 1
    for (int kb = 0; kb < 32; kb++) {
        CP_WAIT(1);              // tile kb landed (tile kb+1 may be in flight)
        __syncthreads();         // visibility + all warps done reading tile kb-1
        if (kb + 2 < 32) { copy_tile(sb, tid, (b == 0) ? 2 : b - 1, kt0 + kb + 2); CP_COMMIT(); }

        const uint32_t kbh = sb + SBUF(b);
        const uint32_t vbh = kbh + 8192;

        // ---- S = qh . kh over all 64 keys ----
        float sc[8][4];
        #pragma unroll
        for (int nb = 0; nb < 8; nb++)
            #pragma unroll
            for (int t = 0; t < 4; t++) sc[nb][t] = 0.f;

        #pragma unroll
        for (int nb = 0; nb < 8; nb++) {
            #pragma unroll
            for (int kcp = 0; kcp < 2; kcp++) {
                uint32_t kf[4];
                LDSM4(kf, swadr(kbh, nb*8 + li, 64*kcp + ls*16));
                MMA(sc[nb], qh[kcp*2 + 0], kf[0], kf[1]);
                MMA(sc[nb], qh[kcp*2 + 1], kf[2], kf[3]);
            }
        }

        // ---- exp (no max; bounded scores) + pack P ----
        uint32_t ph[4][4];
        #pragma unroll
        for (int nb = 0; nb < 8; nb++) {
            float e0 = __expf(sc[nb][0]), e1 = __expf(sc[nb][1]);
            float e2 = __expf(sc[nb][2]), e3 = __expf(sc[nb][3]);
            lg  += e0 + e1;
            lg8 += e2 + e3;
            const int kcl = nb >> 1, rb = (nb & 1) * 2;
            ph[kcl][rb + 0] = pack2(e0, e1);
            ph[kcl][rb + 1] = pack2(e2, e3);
        }

        // ---- O += P V over all 64 keys ----
        #pragma unroll
        for (int kcl = 0; kcl < 4; kcl++) {
            uint32_t vf[4][4];
            #pragma unroll
            for (int dp = 0; dp < 4; dp++)
                LDSM4T(vf[dp], swadr(vbh, kcl*16 + lr*8 + li, 32*dp + lc*16));
            #pragma unroll
            for (int db = 0; db < 8; db++)
                MMA(o[db], ph[kcl], vf[db>>1][(db&1)*2], vf[db>>1][(db&1)*2+1]);
        }

        b = (b == 2) ? 0 : b + 1;
    }

    // ---- epilogue: quad-reduce row sums, store partials ----
    lg  += __shfl_xor_sync(0xffffffffu, lg, 1);
    lg  += __shfl_xor_sync(0xffffffffu, lg, 2);
    lg8 += __shfl_xor_sync(0xffffffffu, lg8, 1);
    lg8 += __shfl_xor_sync(0xffffffffu, lg8, 2);

    const int gq = lane >> 2, t = lane & 3;
    const int n = qb*128 + wid*16 + gq;
    #pragma unroll
    for (int db = 0; db < 8; db++) {
        int d = db*8 + 2*t;
        *reinterpret_cast<float2*>(&g_opart[part][n][d])     = make_float2(o[db][0], o[db][1]);
        *reinterpret_cast<float2*>(&g_opart[part][n + 8][d]) = make_float2(o[db][2], o[db][3]);
    }
    if (t == 0) {
        g_lpart[part][n]     = lg;
        g_lpart[part][n + 8] = lg8;
    }
}

// ---------------- Kernel 3: combine parts + output projection ----------------
__global__ void __launch_bounds__(256) proj_kernel(
    const float* __restrict__ wo, const float* __restrict__ bo,
    float* __restrict__ out)
{
    __shared__ float wt[64*65];
    __shared__ float bs[64];
    __shared__ float os[32*64];
    __shared__ float linv[32];
    const int tid = threadIdx.x;
    const int row0 = blockIdx.x * 32;
    for (int i = tid; i < 4096; i += 256)
        wt[(i >> 6)*65 + (i & 63)] = wo[i];
    if (tid < 64) bs[tid] = bo[tid];
    if (tid < 32) {
        int n = row0 + tid;
        linv[tid] = 1.0f / (g_lpart[0][n] + g_lpart[1][n] + g_lpart[2][n] + g_lpart[3][n]);
    }
    __syncthreads();
    for (int i = tid; i < 2048; i += 256) {
        int row = i >> 6, d = i & 63;
        int n = row0 + row;
        os[i] = (g_opart[0][n][d] + g_opart[1][n][d] + g_opart[2][n][d] + g_opart[3][n][d]) * linv[row];
    }
    __syncthreads();

    for (int tI = tid; tI < 2048; tI += 256) {
        int row = tI >> 6, col = tI & 63;
        float acc = bs[col];
        const float* wrow = &wt[col*65];
        const float* orow = &os[row*64];
        #pragma unroll
        for (int d = 0; d < 64; d++)
            acc = fmaf(orow[d], wrow[d], acc);
        out[(row0 + row)*64 + col] = acc;
    }
}

// ---------------- launch ----------------
extern "C" void kernel_launch(void* const* d_in, const int* in_sizes, int n_in,
                              void* d_out, int out_size)
{
    const float* x  = (const float*)d_in[0];
    const float* wq = (const float*)d_in[1];
    const float* bq = (const float*)d_in[2];
    const float* wk = (const float*)d_in[3];
    const float* bk = (const float*)d_in[4];
    const float* wv = (const float*)d_in[5];
    const float* bv = (const float*)d_in[6];
    const float* th = (const float*)d_in[7];
    const float* wo = (const float*)d_in[8];
    const float* bo = (const float*)d_in[9];
    float* out = (float*)d_out;

    cudaFuncSetAttribute(flash_kernel, cudaFuncAttributeMaxDynamicSharedMemorySize, SMEM_FLASH);

    qkv_kernel<<<dim3(NTOK/32, 3), 256>>>(x, wq, bq, wk, bk, wv, bv, th);
    flash_kernel<<<256, 256, SMEM_FLASH>>>();
    proj_kernel<<<NTOK/32, 256>>>(wo, bo, out);
}

// round 10
// speedup vs baseline: 1.6198x; 1.6198x over previous
#include <cuda_runtime.h>
#include <cuda_bf16.h>
#include <cstdint>

#define NTOK 8192
#define EDIM 64
#define SCALE 0.35355339059327373f   // 1/sqrt(8)
#define NPART 2

// packed bf16x2 words: [row][32 words], SW128-swizzled 16B chunks within 128B rows.
__device__ uint32_t g_qh[NTOK*32];
__device__ uint32_t g_kh[NTOK*32];
__device__ uint32_t g_vh[NTOK*32];
__device__ float    g_opart[NPART][NTOK][EDIM];   // unnormalized O per KV-part
__device__ float    g_lpart[NPART][NTOK];         // softmax denominator per KV-part

// ======================= helpers =======================
__device__ __forceinline__ uint32_t smem_u32(const void* p) {
    uint32_t a;
    asm("{ .reg .u64 t; cvta.to.shared.u64 t, %1; cvt.u32.u64 %0, t; }" : "=r"(a) : "l"(p));
    return a;
}
__device__ __forceinline__ void cp16(uint32_t dst, const void* src) {
    asm volatile("{ .reg .u64 g; cvta.to.global.u64 g, %1; cp.async.cg.shared.global [%0], [g], 16; }"
                 :: "r"(dst), "l"(src) : "memory");
}
#define CP_COMMIT() asm volatile("cp.async.commit_group;" ::: "memory")
#define CP_WAIT(n)  asm volatile("cp.async.wait_group %0;" :: "n"(n) : "memory")

#define LDSM4(r, a) \
    asm volatile("ldmatrix.sync.aligned.m8n8.x4.shared.b16 {%0,%1,%2,%3}, [%4];" \
        : "=r"((r)[0]), "=r"((r)[1]), "=r"((r)[2]), "=r"((r)[3]) : "r"(a))
#define LDSM4T(r, a) \
    asm volatile("ldmatrix.sync.aligned.m8n8.x4.trans.shared.b16 {%0,%1,%2,%3}, [%4];" \
        : "=r"((r)[0]), "=r"((r)[1]), "=r"((r)[2]), "=r"((r)[3]) : "r"(a))

#define MMA(c, a, b0, b1) \
    asm volatile("mma.sync.aligned.m16n8k16.row.col.f32.bf16.bf16.f32 " \
        "{%0,%1,%2,%3}, {%4,%5,%6,%7}, {%8,%9}, {%0,%1,%2,%3};" \
        : "+f"((c)[0]), "+f"((c)[1]), "+f"((c)[2]), "+f"((c)[3]) \
        : "r"((a)[0]), "r"((a)[1]), "r"((a)[2]), "r"((a)[3]), "r"(b0), "r"(b1))

// swizzled smem address: 128B rows, 16B chunk index XOR (row&7)
__device__ __forceinline__ uint32_t swadr(uint32_t base, int row, int bytecol) {
    return base + row*128 + ((((bytecol >> 4) ^ (row & 7)) << 4));
}
__device__ __forceinline__ uint32_t pack2(float a, float b) {
    __nv_bfloat162 p = __floats2bfloat162_rn(a, b);    // x=a (low), y=b (high)
    return *reinterpret_cast<uint32_t*>(&p);
}

// smem: Qh 0..8K ; buf b (b=0..2) at 8192 + b*16384 : [Kh 8K | Vh 8K]
#define SBUF(b)    (8192 + (b)*16384)
#define SMEM_FLASH 57344

// ---------------- Kernel 1: QKV projection + quantum map + bf16 packing ----------------
// 256 thr, 64 rows/block; thread: rows rg, rg+32 x cols c0..c0+7.
__global__ void __launch_bounds__(256) qkv_kernel(
    const float* __restrict__ x,
    const float* __restrict__ wq, const float* __restrict__ bq,
    const float* __restrict__ wk, const float* __restrict__ bk,
    const float* __restrict__ wv, const float* __restrict__ bv,
    const float* __restrict__ theta)
{
    __shared__ float wtT[64*64];   // [d][col] (transposed: per-warp broadcast float4)
    __shared__ float xs[64*65];    // [row][d] stride 65 (conflict-free scalar)
    __shared__ float bs[64];
    __shared__ float cs[64];

    const int tid  = threadIdx.x;
    const int m    = blockIdx.y;
    const int row0 = blockIdx.x * 64;

    const float* w  = (m == 0) ? wq : ((m == 1) ? wk : wv);
    const float* bb = (m == 0) ? bq : ((m == 1) ? bk : bv);
    for (int i = tid; i < 4096; i += 256) {
        int col = i >> 6, d = i & 63;
        wtT[d*64 + col] = w[i];
    }
    if (tid < 64) {
        bs[tid] = bb[tid];
        cs[tid] = ((m == 0) ? SCALE : 1.0f) * __cosf(theta[tid]);
    }
    for (int i = tid; i < 4096; i += 256)
        xs[(i >> 6)*65 + (i & 63)] = x[(size_t)row0*64 + i];
    __syncthreads();

    const int rg = tid & 31;
    const int c0 = (tid >> 5) * 8;

    float acc[2][8];
    #pragma unroll
    for (int i = 0; i < 2; i++)
        #pragma unroll
        for (int j = 0; j < 8; j++) acc[i][j] = bs[c0 + j];

    #pragma unroll
    for (int d4 = 0; d4 < 64; d4 += 4) {
        float x0[4], x1[4];
        #pragma unroll
        for (int j = 0; j < 4; j++) {
            x0[j] = xs[rg*65 + d4 + j];          // bank (rg + d) % 32: conflict-free
            x1[j] = xs[(rg + 32)*65 + d4 + j];
        }
        #pragma unroll
        for (int j = 0; j < 4; j++) {
            float4 wA = *reinterpret_cast<float4*>(&wtT[(d4 + j)*64 + c0]);      // broadcast
            float4 wB = *reinterpret_cast<float4*>(&wtT[(d4 + j)*64 + c0 + 4]);  // broadcast
            float wv8[8] = {wA.x, wA.y, wA.z, wA.w, wB.x, wB.y, wB.z, wB.w};
            #pragma unroll
            for (int k = 0; k < 8; k++) {
                acc[0][k] = fmaf(x0[j], wv8[k], acc[0][k]);
                acc[1][k] = fmaf(x1[j], wv8[k], acc[1][k]);
            }
        }
    }

    uint32_t* dst = (m == 0) ? g_qh : ((m == 1) ? g_kh : g_vh);
    #pragma unroll
    for (int i = 0; i < 2; i++) {
        const int gr = row0 + rg + 32*i;
        float v[8];
        #pragma unroll
        for (int j = 0; j < 8; j++)
            v[j] = cs[c0 + j] * __cosf(acc[i][j]);
        const int wd0 = ((((c0 >> 3) ^ (gr & 7)) << 2));
        #pragma unroll
        for (int p = 0; p < 4; p++)
            dst[gr*32 + wd0 + p] = pack2(v[2*p], v[2*p + 1]);
    }
}

// ---------------- tile copy: 64 keys x (Kh, Vh), pre-swizzled ----------------
__device__ __forceinline__ void copy_tile(uint32_t sb, int tid, int buf, int kt) {
    #pragma unroll
    for (int j = 0; j < 4; j++) {
        int c = j*256 + tid;        // 0..1023
        int arr = c >> 9;           // 0:kh 1:vh (constant per j)
        int rem = c & 511;
        int row = rem >> 3, ch = rem & 7;
        const uint32_t* sp = arr ? g_vh : g_kh;
        cp16(sb + SBUF(buf) + arr*8192 + row*128 + ch*16,
             sp + (size_t)(kt*64 + row)*32 + ch*4);
    }
}

// ---------------- Kernel 2: bf16 flash attention, split-KV x2, single-sync loop ------
__global__ void __launch_bounds__(256, 2) flash_kernel()
{
    extern __shared__ char smem[];
    uint32_t sb = smem_u32(smem);
    const int tid  = threadIdx.x;
    const int wid  = tid >> 5;
    const int lane = tid & 31;
    const int qb   = blockIdx.x >> 1;       // 64 q-rows per CTA
    const int part = blockIdx.x & 1;        // KV half: tiles part*64 .. +63
    const int kt0  = part * 64;
    const int kg   = wid >> 2;              // key group: 0 -> keys 0-31, 1 -> keys 32-63
    const int wq4  = wid & 3;               // q-row quarter: rows wq4*16..+15

    // ---- prologue copies: Qh, tiles 0,1 ----
    #pragma unroll
    for (int j = 0; j < 2; j++) {
        int c = j*256 + tid;
        int row = c >> 3, ch = c & 7;
        cp16(sb + row*128 + ch*16, g_qh + (size_t)(qb*64 + row)*32 + ch*4);
    }
    CP_COMMIT();
    copy_tile(sb, tid, 0, kt0 + 0); CP_COMMIT();
    copy_tile(sb, tid, 1, kt0 + 1); CP_COMMIT();
    CP_WAIT(2);                  // Q landed
    __syncthreads();

    // ---- Q A-fragments (persistent) ----
    uint32_t qh[4][4];
    {
        const int row = wq4*16 + (lane & 15);
        const int cb  = (lane >> 4) * 16;
        #pragma unroll
        for (int kc = 0; kc < 4; kc++)
            LDSM4(qh[kc], swadr(sb, row, 32*kc + cb));
    }

    float o[8][4];
    #pragma unroll
    for (int db = 0; db < 8; db++)
        #pragma unroll
        for (int i = 0; i < 4; i++) o[db][i] = 0.f;
    float lg = 0.f, lg8 = 0.f;

    const int li = lane & 7, ls = lane >> 3;
    const int lr = (lane >> 3) & 1, lc = lane >> 4;
    const int nb0 = kg * 4;

    int b = 0;
    #pragma unroll 1
    for (int kb = 0; kb < 64; kb++) {
        CP_WAIT(1);              // tile kb landed (kb+1 may be in flight)
        __syncthreads();         // all warps past tile kb-1; kb visible everywhere
        if (kb + 2 < 64) {       // refill the buffer freed by tile kb-1
            int nbuf = (b == 2) ? 0 : b + 1;
            int pbuf = (nbuf == 2) ? 0 : nbuf + 1;   // (kb+2)%3
            copy_tile(sb, tid, pbuf, kt0 + kb + 2); CP_COMMIT();
        }

        const uint32_t kbh = sb + SBUF(b);
        const uint32_t vbh = kbh + 8192;

        // ---- S = qh . kh over this group's 32 keys ----
        float sc[4][4];
        #pragma unroll
        for (int ln = 0; ln < 4; ln++)
            #pragma unroll
            for (int t = 0; t < 4; t++) sc[ln][t] = 0.f;

        #pragma unroll
        for (int ln = 0; ln < 4; ln++) {
            const int nb = nb0 + ln;
            #pragma unroll
            for (int kcp = 0; kcp < 2; kcp++) {
                uint32_t kf[4];
                LDSM4(kf, swadr(kbh, nb*8 + li, 64*kcp + ls*16));
                MMA(sc[ln], qh[kcp*2 + 0], kf[0], kf[1]);
                MMA(sc[ln], qh[kcp*2 + 1], kf[2], kf[3]);
            }
        }

        // ---- exp (no max; bounded scores) + pack P ----
        uint32_t ph[2][4];
        #pragma unroll
        for (int ln = 0; ln < 4; ln++) {
            float e0 = __expf(sc[ln][0]), e1 = __expf(sc[ln][1]);
            float e2 = __expf(sc[ln][2]), e3 = __expf(sc[ln][3]);
            lg  += e0 + e1;
            lg8 += e2 + e3;
            const int kcl = ln >> 1, rb = (ln & 1) * 2;
            ph[kcl][rb + 0] = pack2(e0, e1);
            ph[kcl][rb + 1] = pack2(e2, e3);
        }

        // ---- O += P V over this group's 32 keys ----
        #pragma unroll
        for (int kcl = 0; kcl < 2; kcl++) {
            const int kcg = kg*2 + kcl;
            uint32_t vf[4][4];
            #pragma unroll
            for (int dp = 0; dp < 4; dp++)
                LDSM4T(vf[dp], swadr(vbh, kcg*16 + lr*8 + li, 32*dp + lc*16));
            #pragma unroll
            for (int db = 0; db < 8; db++)
                MMA(o[db], ph[kcl], vf[db>>1][(db&1)*2], vf[db>>1][(db&1)*2+1]);
        }

        b = (b == 2) ? 0 : b + 1;
    }

    // ---- reduce l within quad ----
    lg  += __shfl_xor_sync(0xffffffffu, lg, 1);
    lg  += __shfl_xor_sync(0xffffffffu, lg, 2);
    lg8 += __shfl_xor_sync(0xffffffffu, lg8, 1);
    lg8 += __shfl_xor_sync(0xffffffffu, lg8, 2);

    // ---- cross-keygroup reduction via smem (buffers are free now) ----
    float* red  = (float*)(smem + 8192);             // [4][32][32] = 16KB
    float* redl = (float*)(smem + 8192 + 16384);     // [4][32][2]
    __syncthreads();
    if (kg == 1) {
        float* dst = red + (wq4*32 + lane)*32;
        #pragma unroll
        for (int db = 0; db < 8; db++)
            #pragma unroll
            for (int t = 0; t < 4; t++) dst[db*4 + t] = o[db][t];
        redl[(wq4*32 + lane)*2 + 0] = lg;
        redl[(wq4*32 + lane)*2 + 1] = lg8;
    }
    __syncthreads();
    if (kg == 0) {
        const float* src = red + (wq4*32 + lane)*32;
        #pragma unroll
        for (int db = 0; db < 8; db++)
            #pragma unroll
            for (int t = 0; t < 4; t++) o[db][t] += src[db*4 + t];
        lg  += redl[(wq4*32 + lane)*2 + 0];
        lg8 += redl[(wq4*32 + lane)*2 + 1];

        const int gq = lane >> 2, t = lane & 3;
        const int n = qb*64 + wq4*16 + gq;
        #pragma unroll
        for (int db = 0; db < 8; db++) {
            int d = db*8 + 2*t;
            *reinterpret_cast<float2*>(&g_opart[part][n][d])     = make_float2(o[db][0], o[db][1]);
            *reinterpret_cast<float2*>(&g_opart[part][n + 8][d]) = make_float2(o[db][2], o[db][3]);
        }
        if (t == 0) {
            g_lpart[part][n]     = lg;
            g_lpart[part][n + 8] = lg8;
        }
    }
}

// ---------------- Kernel 3: combine halves + output projection ----------------
__global__ void __launch_bounds__(256) proj_kernel(
    const float* __restrict__ wo, const float* __restrict__ bo,
    float* __restrict__ out)
{
    __shared__ float wt[64*65];
    __shared__ float bs[64];
    __shared__ float os[32*64];
    __shared__ float linv[32];
    const int tid = threadIdx.x;
    const int row0 = blockIdx.x * 32;
    for (int i = tid; i < 4096; i += 256)
        wt[(i >> 6)*65 + (i & 63)] = wo[i];
    if (tid < 64) bs[tid] = bo[tid];
    if (tid < 32) {
        int n = row0 + tid;
        linv[tid] = 1.0f / (g_lpart[0][n] + g_lpart[1][n]);
    }
    __syncthreads();
    for (int i = tid; i < 2048; i += 256) {
        int row = i >> 6, d = i & 63;
        int n = row0 + row;
        os[i] = (g_opart[0][n][d] + g_opart[1][n][d]) * linv[row];
    }
    __syncthreads();

    for (int tI = tid; tI < 2048; tI += 256) {
        int row = tI >> 6, col = tI & 63;
        float acc = bs[col];
        const float* wrow = &wt[col*65];
        const float* orow = &os[row*64];
        #pragma unroll
        for (int d = 0; d < 64; d++)
            acc = fmaf(orow[d], wrow[d], acc);
        out[(row0 + row)*64 + col] = acc;
    }
}

// ---------------- launch ----------------
extern "C" void kernel_launch(void* const* d_in, const int* in_sizes, int n_in,
                              void* d_out, int out_size)
{
    const float* x  = (const float*)d_in[0];
    const float* wq = (const float*)d_in[1];
    const float* bq = (const float*)d_in[2];
    const float* wk = (const float*)d_in[3];
    const float* bk = (const float*)d_in[4];
    const float* wv = (const float*)d_in[5];
    const float* bv = (const float*)d_in[6];
    const float* th = (const float*)d_in[7];
    const float* wo = (const float*)d_in[8];
    const float* bo = (const float*)d_in[9];
    float* out = (float*)d_out;

    cudaFuncSetAttribute(flash_kernel, cudaFuncAttributeMaxDynamicSharedMemorySize, SMEM_FLASH);

    qkv_kernel<<<dim3(NTOK/64, 3), 256>>>(x, wq, bq, wk, bk, wv, bv, th);
    flash_kernel<<<256, 256, SMEM_FLASH>>>();
    proj_kernel<<<NTOK/32, 256>>>(wo, bo, out);
}